// round 16
// baseline (speedup 1.0000x reference)
#include <cuda_runtime.h>

// InpatientInterventions on GB300 (sm_103a) — persistent fused kernel, v3.
// out[t,g] = sum_e rate[e]*weights[index[e]] * [start<=t0[t]<end], g=group_id[index[e]]
// t0 sorted -> each event covers a contiguous t-range [t_lo, t_hi).
//
// v3: fully deterministic dense endpoint list (slot 2e/2e+1, no atomics, no
// counters, no scratch zeroing). Each writer block scans the whole list and
// classifies endpoints against its private row window: t < r0 -> base row,
// r0 <= t < r0+TC -> tile row. Empty ranges self-cancel (+c/-c same cell);
// t==T endpoints are natural no-ops. ONE grid barrier total.

#define NB      148            // grid size == co-resident SM count
#define BT      1024           // threads per block
#define TC      28             // rows per writer chunk -> nchunk=147 for T=4096
#define EMAX    32768

// dense endpoint list: entry e = {x1,y1,x2,y2}
//   x = (t << 10) | g   (g < 1024),  y = float bits of +/-c
__device__ uint4 g_ep[EMAX];

// self-resetting grid barrier state (returns to 0 every launch)
__device__ unsigned g_arrive;
__device__ unsigned g_release;
__device__ unsigned g_depart;

__device__ __forceinline__ void grid_barrier()
{
    __threadfence();
    __syncthreads();
    if (threadIdx.x == 0) {
        unsigned old = atomicInc(&g_arrive, NB - 1);     // wraps to 0 at NB
        if (old == NB - 1) {
            atomicExch(&g_release, 1u);
        } else {
            while (atomicAdd(&g_release, 0u) == 0u)
                __nanosleep(32);
        }
        unsigned d = atomicInc(&g_depart, NB - 1);       // wraps to 0 at NB
        if (d == NB - 1)
            atomicExch(&g_release, 0u);
    }
    __syncthreads();
    __threadfence();
}

__global__ void __launch_bounds__(BT, 1)
fused(const int*   __restrict__ index,
      const float* __restrict__ rate,
      const float* __restrict__ start,
      const float* __restrict__ endt,
      const float* __restrict__ t0,
      const int*   __restrict__ group_id,
      const float* __restrict__ weights,
      float*       __restrict__ out,
      int E, int T, int G)
{
    extern __shared__ float smem[];    // ph1: t0 stage (16KB). ph2: (TC+1) x G tile
    const int b   = blockIdx.x;
    const int tid = threadIdx.x;

    // ---------------- phase 1: deterministic endpoint emit ----------------
    {
        for (int i = tid; i < T; i += BT)       // stage t0 into smem
            smem[i] = t0[i];
        __syncthreads();

        const int per = (E + NB - 1) / NB;      // contiguous events per block
        int e = b * per + tid;
        if (tid < per && e < E) {
            float s  = start[e];
            float en = endt[e];

            // two interleaved lower_bounds on smem t0
            int lo1 = 0, hi1 = T, lo2 = 0, hi2 = T;
            #pragma unroll 1
            while ((lo1 < hi1) | (lo2 < hi2)) {
                if (lo1 < hi1) { int m = (lo1 + hi1) >> 1;
                                 if (smem[m] < s)  lo1 = m + 1; else hi1 = m; }
                if (lo2 < hi2) { int m = (lo2 + hi2) >> 1;
                                 if (smem[m] < en) lo2 = m + 1; else hi2 = m; }
            }
            // t_lo == t_hi  -> pair cancels in the writer; t == T -> no-op.
            int   src = __ldg(&index[e]);
            float c   = rate[e] * __ldg(&weights[src]);
            int   g   = __ldg(&group_id[src]);

            g_ep[e] = make_uint4((unsigned)((lo1 << 10) | g), __float_as_uint(c),
                                 (unsigned)((lo2 << 10) | g), __float_as_uint(-c));
        }
    }

    grid_barrier();

    // ---------------- phase 2: writer (one (TC x G) tile per block) ---------
    const int nchunk = (T + TC - 1) / TC;       // 147 for T=4096
    float* base = smem + TC * G;                // extra row: exclusive base
    for (int ch = b; ch < nchunk; ch += NB) {
        // zero tile + base row
        float4* t4 = (float4*)smem;
        const int nz4 = ((TC + 1) * G) / 4;
        #pragma unroll 8
        for (int i = tid; i < nz4; i += BT)
            t4[i] = make_float4(0.f, 0.f, 0.f, 0.f);
        __syncthreads();

        const int r0 = ch * TC;

        // scan the full dense endpoint list (L2-broadcast across blocks)
        #pragma unroll 2
        for (int i = tid; i < E; i += BT) {
            uint4 kv = g_ep[i];
            {
                int t = (int)(kv.x >> 10), g = (int)(kv.x & 1023u);
                int rr = t - r0;
                if (rr < 0)        atomicAdd(&base[g], __uint_as_float(kv.y));
                else if (rr < TC)  atomicAdd(&smem[rr * G + g], __uint_as_float(kv.y));
            }
            {
                int t = (int)(kv.z >> 10), g = (int)(kv.z & 1023u);
                int rr = t - r0;
                if (rr < 0)        atomicAdd(&base[g], __uint_as_float(kv.w));
                else if (rr < TC)  atomicAdd(&smem[rr * G + g], __uint_as_float(kv.w));
            }
        }
        __syncthreads();

        // per-column prefix scan + coalesced write-only output
        int g = tid;
        if (g < G) {
            float acc = base[g];
            int rend = min(TC, T - r0);
            #pragma unroll 7
            for (int r = 0; r < rend; ++r) {
                acc += smem[r * G + g];
                out[(size_t)(r0 + r) * G + g] = acc;
            }
        }
        __syncthreads();   // tile consumed before a (rare) next iteration
    }
}

// -----------------------------------------------------------------------------
extern "C" void kernel_launch(void* const* d_in, const int* in_sizes, int n_in,
                              void* d_out, int out_size)
{
    const int*   index    = (const int*)  d_in[0];
    const float* rate     = (const float*)d_in[1];
    const float* start    = (const float*)d_in[2];
    const float* endt     = (const float*)d_in[3];
    const float* t0       = (const float*)d_in[4];
    const int*   group_id = (const int*)  d_in[5];
    const float* weights  = (const float*)d_in[6];
    float*       out      = (float*)d_out;

    int E = in_sizes[0];
    int T = in_sizes[4];
    int G = out_size / T;                       // 1024

    const int smem_bytes = (TC + 1) * G * (int)sizeof(float);   // 118,784 B
    cudaFuncSetAttribute(fused, cudaFuncAttributeMaxDynamicSharedMemorySize,
                         smem_bytes);

    fused<<<NB, BT, smem_bytes>>>(index, rate, start, endt, t0,
                                  group_id, weights, out, E, T, G);
}